// round 10
// baseline (speedup 1.0000x reference)
#include <cuda_runtime.h>
#include <cuda_fp16.h>
#include <math.h>

#define N_USER   100000
#define N_ITEM   50000
#define N_NODES_ (N_USER + N_ITEM)   // 150000
#define NNZ_     4800000
#define EMB      64
#define N_LAYERS 3
#define BATCH_   16384
#define EPS_     1e-12f
#define NEG_SLOPE 0.2f

// ---------------- scratch (device globals: allocation-free rule) -------------
__device__ float  g_ego  [N_NODES_ * EMB];      // fp32 layer input (unnormalized)
__device__ __half g_ego_h[N_NODES_ * EMB];      // fp16 shadow for spmm gathers
__device__ float  g_side [N_NODES_ * EMB];      // A_hat @ ego (written whole by CSR spmm)
__device__ float  g_all  [N_NODES_ * 4 * EMB];  // concat of 4 embedding blocks
// CSR build scratch.  g_row_cnt is zero-initialized at module load and
// re-zeroed by scan_kernel after it is consumed -> every replay sees zeros.
__device__ int   g_row_cnt[N_NODES_];
__device__ int   g_row_cur[N_NODES_];           // seeded with row offsets by scan
__device__ int   g_row_off[N_NODES_ + 1];
__device__ int2  g_edge_s [NNZ_];               // packed (col, val_bits), row-sorted

// ------- init: ego = concat(user_emb, item_emb) (fp32 + fp16 shadow) ---------
// Also fuses the degree count (first NNZ/4 threads handle one edge-quad each).
__global__ void init_kernel(const float* __restrict__ ue, const float* __restrict__ ie,
                            const int* __restrict__ rows) {
    int idx = blockIdx.x * blockDim.x + threadIdx.x;      // float4 / half4 index
    const int total = N_NODES_ * EMB / 4;                 // 2.4M
    if (idx < total) {
        int node = idx >> 4;
        int c4   = idx & 15;
        float4 v;
        if (node < N_USER) v = __ldg((const float4*)ue + node * 16 + c4);
        else               v = __ldg((const float4*)ie + (node - N_USER) * 16 + c4);
        ((float4*)g_ego)[idx] = v;
        ((float4*)g_all)[node * 64 + c4] = v;
        __half2 h0 = __floats2half2_rn(v.x, v.y);
        __half2 h1 = __floats2half2_rn(v.z, v.w);
        uint2 pk;
        pk.x = *(unsigned*)&h0;
        pk.y = *(unsigned*)&h1;
        ((uint2*)g_ego_h)[idx] = pk;
    }
    if (idx < NNZ_ / 4) {             // fused degree count (cnt pre-zeroed)
        int4 r4 = __ldg((const int4*)rows + idx);
        atomicAdd(&g_row_cnt[r4.x], 1);
        atomicAdd(&g_row_cnt[r4.y], 1);
        atomicAdd(&g_row_cnt[r4.z], 1);
        atomicAdd(&g_row_cnt[r4.w], 1);
    }
}

// ---------------- CSR build: exclusive scan (single block, 1024 threads) -----
// R8-style: no per-thread local array (that spilled in R9).  Reads g_row_cnt
// twice from L2; second pass zeroes it for the next graph replay and seeds
// g_row_cur with the row offsets (scatter cursor trick).
__global__ void scan_kernel() {
    __shared__ int part[1024];
    const int CH = (N_NODES_ + 1023) / 1024;   // 147
    int t = threadIdx.x;
    int base = t * CH;
    int s = 0;
    for (int i = 0; i < CH; i++) {
        int idx = base + i;
        if (idx < N_NODES_) s += g_row_cnt[idx];
    }
    part[t] = s;
    __syncthreads();
    for (int off = 1; off < 1024; off <<= 1) {
        int u = (t >= off) ? part[t - off] : 0;
        __syncthreads();
        part[t] += u;
        __syncthreads();
    }
    int run = part[t] - s;          // exclusive prefix for this chunk
    for (int i = 0; i < CH; i++) {
        int idx = base + i;
        if (idx < N_NODES_) {
            int c = g_row_cnt[idx];
            g_row_cnt[idx] = 0;     // reset for next replay
            g_row_off[idx] = run;
            g_row_cur[idx] = run;   // cursor starts at row start
            run += c;
        }
    }
    if (t == 1023) g_row_off[N_NODES_] = part[1023];   // total = NNZ
}

// ---------------- CSR build: scatter edges (R6-measured version) --------------
// 8 independent atomic->store chains per thread; position comes straight from
// the cursor atomic; one packed int2 store per edge.
__global__ void scatter_kernel(const int* __restrict__ rows,
                               const int* __restrict__ cols,
                               const int* __restrict__ vals) {
    int q = blockIdx.x * blockDim.x + threadIdx.x;   // octet id
    if (q >= NNZ_ / 8) return;
    int4 ra = __ldg((const int4*)rows + q * 2);
    int4 rb = __ldg((const int4*)rows + q * 2 + 1);
    int4 ca = __ldg((const int4*)cols + q * 2);
    int4 cb = __ldg((const int4*)cols + q * 2 + 1);
    int4 va = __ldg((const int4*)vals + q * 2);      // val bits
    int4 vb = __ldg((const int4*)vals + q * 2 + 1);
    int r[8] = {ra.x, ra.y, ra.z, ra.w, rb.x, rb.y, rb.z, rb.w};
    int c[8] = {ca.x, ca.y, ca.z, ca.w, cb.x, cb.y, cb.z, cb.w};
    int v[8] = {va.x, va.y, va.z, va.w, vb.x, vb.y, vb.z, vb.w};
    int p[8];
#pragma unroll
    for (int u = 0; u < 8; u++) p[u] = atomicAdd(&g_row_cur[r[u]], 1);
#pragma unroll
    for (int u = 0; u < 8; u++) g_edge_s[p[u]] = make_int2(c[u], v[u]);
}

// ---------------- CSR SpMM: fp16 gather, fp32 accumulate (R9-measured 63us) ---
// 16 lanes per row; packed int2 edge loads; 4-edge unroll (MLP=4, low regs).
__global__ void spmm_csr_kernel() {
    int t = blockIdx.x * blockDim.x + threadIdx.x;
    int r = t >> 4;                 // row id (grid sized exactly)
    int l = t & 15;
    int beg = __ldg(&g_row_off[r]);
    int end = __ldg(&g_row_off[r + 1]);
    float4 acc = make_float4(0.f, 0.f, 0.f, 0.f);
    int e = beg;
    for (; e + 4 <= end; e += 4) {
        int2 E0 = __ldg(&g_edge_s[e + 0]);
        int2 E1 = __ldg(&g_edge_s[e + 1]);
        int2 E2 = __ldg(&g_edge_s[e + 2]);
        int2 E3 = __ldg(&g_edge_s[e + 3]);
        uint2 w0 = __ldg((const uint2*)g_ego_h + E0.x * 16 + l);
        uint2 w1 = __ldg((const uint2*)g_ego_h + E1.x * 16 + l);
        uint2 w2 = __ldg((const uint2*)g_ego_h + E2.x * 16 + l);
        uint2 w3 = __ldg((const uint2*)g_ego_h + E3.x * 16 + l);
        float v0 = __int_as_float(E0.y);
        float v1 = __int_as_float(E1.y);
        float v2 = __int_as_float(E2.y);
        float v3 = __int_as_float(E3.y);
        float2 a0 = __half22float2(*(const __half2*)&w0.x);
        float2 b0 = __half22float2(*(const __half2*)&w0.y);
        float2 a1 = __half22float2(*(const __half2*)&w1.x);
        float2 b1 = __half22float2(*(const __half2*)&w1.y);
        float2 a2 = __half22float2(*(const __half2*)&w2.x);
        float2 b2 = __half22float2(*(const __half2*)&w2.y);
        float2 a3 = __half22float2(*(const __half2*)&w3.x);
        float2 b3 = __half22float2(*(const __half2*)&w3.y);
        acc.x += a0.x * v0 + a1.x * v1 + a2.x * v2 + a3.x * v3;
        acc.y += a0.y * v0 + a1.y * v1 + a2.y * v2 + a3.y * v3;
        acc.z += b0.x * v0 + b1.x * v1 + b2.x * v2 + b3.x * v3;
        acc.w += b0.y * v0 + b1.y * v1 + b2.y * v2 + b3.y * v3;
    }
    for (; e < end; e++) {
        int2 E = __ldg(&g_edge_s[e]);
        float v = __int_as_float(E.y);
        uint2 w = __ldg((const uint2*)g_ego_h + E.x * 16 + l);
        float2 a = __half22float2(*(const __half2*)&w.x);
        float2 b = __half22float2(*(const __half2*)&w.y);
        acc.x += a.x * v; acc.y += a.y * v; acc.z += b.x * v; acc.w += b.y * v;
    }
    ((float4*)g_side)[r * 16 + l] = acc;
}

// ---------------- fused dense transform + leaky_relu + L2-normalize ----------
// R1-measured structure (92us). Epilogue refreshes the fp16 shadow of ego
// for the next layer's spmm (layers 0,1 only).
__global__ void transform_kernel(const float* __restrict__ Wgc,
                                 const float* __restrict__ bgc,
                                 const float* __restrict__ Wbi,
                                 const float* __restrict__ bbi,
                                 int layer) {
    extern __shared__ float sh[];
    float* Ssh = sh;                    // [64][65]
    float* Psh = Ssh + 64 * 65;         // [64][65]
    float* Wg  = Psh + 64 * 65;         // [64][64]
    float* Wb  = Wg  + 64 * 64;         // [64][64]
    float* bs  = Wb  + 64 * 64;         // [64]

    const int tid = threadIdx.x;
    const int rowBase = blockIdx.x * 64;

    for (int i = tid; i < 1024; i += 256) {
        ((float4*)Wg)[i] = __ldg((const float4*)Wgc + i);
        ((float4*)Wb)[i] = __ldg((const float4*)Wbi + i);
    }
    if (tid < 64) bs[tid] = __ldg(bgc + tid) + __ldg(bbi + tid);

    for (int i = tid; i < 1024; i += 256) {
        int r  = i >> 4;
        int c4 = i & 15;
        int gr = rowBase + r;
        float4 s = make_float4(0.f, 0.f, 0.f, 0.f);
        float4 e = make_float4(0.f, 0.f, 0.f, 0.f);
        if (gr < N_NODES_) {
            s = ((const float4*)g_side)[gr * 16 + c4];
            e = ((const float4*)g_ego )[gr * 16 + c4];
        }
        float* sp = Ssh + r * 65 + c4 * 4;
        sp[0] = s.x; sp[1] = s.y; sp[2] = s.z; sp[3] = s.w;
        float* pp = Psh + r * 65 + c4 * 4;
        pp[0] = e.x * s.x; pp[1] = e.y * s.y; pp[2] = e.z * s.z; pp[3] = e.w * s.w;
    }
    __syncthreads();

    const int tx = tid & 15;
    const int ty = tid >> 4;
    float acc[4][4];
#pragma unroll
    for (int i = 0; i < 4; i++)
#pragma unroll
        for (int j = 0; j < 4; j++) acc[i][j] = 0.f;

#pragma unroll 8
    for (int k = 0; k < 64; k++) {
        float4 bg = *(const float4*)&Wg[k * 64 + tx * 4];
        float4 bb = *(const float4*)&Wb[k * 64 + tx * 4];
        float as[4], ap[4];
#pragma unroll
        for (int i = 0; i < 4; i++) {
            as[i] = Ssh[(ty * 4 + i) * 65 + k];
            ap[i] = Psh[(ty * 4 + i) * 65 + k];
        }
#pragma unroll
        for (int i = 0; i < 4; i++) {
            acc[i][0] += as[i] * bg.x + ap[i] * bb.x;
            acc[i][1] += as[i] * bg.y + ap[i] * bb.y;
            acc[i][2] += as[i] * bg.z + ap[i] * bb.z;
            acc[i][3] += as[i] * bg.w + ap[i] * bb.w;
        }
    }

    const int colBase = tx * 4;
    float v[4][4];
    float sq[4];
#pragma unroll
    for (int i = 0; i < 4; i++) {
        float x0 = acc[i][0] + bs[colBase + 0];
        float x1 = acc[i][1] + bs[colBase + 1];
        float x2 = acc[i][2] + bs[colBase + 2];
        float x3 = acc[i][3] + bs[colBase + 3];
        x0 = fmaxf(x0, NEG_SLOPE * x0);
        x1 = fmaxf(x1, NEG_SLOPE * x1);
        x2 = fmaxf(x2, NEG_SLOPE * x2);
        x3 = fmaxf(x3, NEG_SLOPE * x3);
        v[i][0] = x0; v[i][1] = x1; v[i][2] = x2; v[i][3] = x3;
        float s = x0 * x0 + x1 * x1 + x2 * x2 + x3 * x3;
#pragma unroll
        for (int off = 1; off < 16; off <<= 1)
            s += __shfl_xor_sync(0xffffffffu, s, off);
        sq[i] = s;
    }

#pragma unroll
    for (int i = 0; i < 4; i++) {
        int gr = rowBase + ty * 4 + i;
        if (gr >= N_NODES_) continue;
        float inv = 1.0f / fmaxf(sqrtf(sq[i]), EPS_);
        float4 raw = make_float4(v[i][0], v[i][1], v[i][2], v[i][3]);
        float4 nrm = make_float4(v[i][0] * inv, v[i][1] * inv, v[i][2] * inv, v[i][3] * inv);
        *(float4*)&g_ego[(size_t)gr * EMB + colBase] = raw;
        *(float4*)&g_all[(size_t)gr * 256 + (layer + 1) * 64 + colBase] = nrm;
        if (layer < N_LAYERS - 1) {
            __half2 h0 = __floats2half2_rn(raw.x, raw.y);
            __half2 h1 = __floats2half2_rn(raw.z, raw.w);
            uint2 pk;
            pk.x = *(unsigned*)&h0;
            pk.y = *(unsigned*)&h1;
            *(uint2*)&g_ego_h[(size_t)gr * EMB + colBase] = pk;
        }
    }
}

// ---------------- GMF head: sigmoid((u*i)@W_out + b_out) ---------------------
__global__ void head_kernel(const int* __restrict__ uidx,
                            const int* __restrict__ iidx,
                            const float* __restrict__ Wout,
                            const float* __restrict__ bout,
                            float* __restrict__ out) {
    int gw = (blockIdx.x * blockDim.x + threadIdx.x) >> 5;
    if (gw >= BATCH_) return;
    int lane = threadIdx.x & 31;
    int u  = __ldg(&uidx[gw]);
    int it = __ldg(&iidx[gw]) + N_USER;
    const float4* ur = (const float4*)(g_all + (size_t)u  * 256);
    const float4* ir = (const float4*)(g_all + (size_t)it * 256);
    const float4* w4 = (const float4*)Wout;
    float acc = 0.f;
#pragma unroll
    for (int q = 0; q < 2; q++) {
        int c = lane + q * 32;
        float4 a = ur[c];
        float4 b = ir[c];
        float4 w = __ldg(&w4[c]);
        acc += a.x * b.x * w.x + a.y * b.y * w.y + a.z * b.z * w.z + a.w * b.w * w.w;
    }
#pragma unroll
    for (int off = 16; off; off >>= 1)
        acc += __shfl_xor_sync(0xffffffffu, acc, off);
    if (lane == 0) {
        float z = acc + __ldg(bout);
        out[gw] = 1.0f / (1.0f + expf(-z));
    }
}

// ---------------- launch ------------------------------------------------------
extern "C" void kernel_launch(void* const* d_in, const int* in_sizes, int n_in,
                              void* d_out, int out_size) {
    const int*   user_idx = (const int*)  d_in[0];
    const int*   item_idx = (const int*)  d_in[1];
    const int*   adj_rows = (const int*)  d_in[2];
    const int*   adj_cols = (const int*)  d_in[3];
    const int*   adj_vals = (const int*)  d_in[4];   // raw bits for scatter
    const float* user_emb = (const float*)d_in[5];
    const float* item_emb = (const float*)d_in[6];
    const float* W_gc     = (const float*)d_in[7];
    const float* b_gc     = (const float*)d_in[8];
    const float* W_bi     = (const float*)d_in[9];
    const float* b_bi     = (const float*)d_in[10];
    const float* W_out    = (const float*)d_in[11];
    const float* b_out    = (const float*)d_in[12];
    float* out = (float*)d_out;

    const int smem = (64 * 65 * 2 + 64 * 64 * 2 + 64) * (int)sizeof(float);  // 66304 B
    cudaFuncSetAttribute(transform_kernel,
                         cudaFuncAttributeMaxDynamicSharedMemorySize, smem);

    const int vec_blocks = (N_NODES_ * EMB / 4) / 256;   // 9375 (covers NNZ/4=1.2M too)
    init_kernel<<<vec_blocks, 256>>>(user_emb, item_emb, adj_rows);

    scan_kernel<<<1, 1024>>>();
    scatter_kernel<<<(NNZ_ / 8 + 255) / 256, 256>>>(adj_rows, adj_cols, adj_vals);

    const int spmm_blocks = (N_NODES_ * 16) / 256;       // 9375 exactly
    const int tile_blocks = (N_NODES_ + 63) / 64;        // 2344

    for (int l = 0; l < N_LAYERS; l++) {
        spmm_csr_kernel<<<spmm_blocks, 256>>>();
        transform_kernel<<<tile_blocks, 256, smem>>>(W_gc + l * EMB * EMB,
                                                     b_gc + l * EMB,
                                                     W_bi + l * EMB * EMB,
                                                     b_bi + l * EMB,
                                                     l);
    }

    head_kernel<<<(BATCH_ * 32) / 256, 256>>>(user_idx, item_idx, W_out, b_out, out);
}

// round 11
// speedup vs baseline: 1.2563x; 1.2563x over previous
#include <cuda_runtime.h>
#include <cuda_fp16.h>
#include <math.h>

#define N_USER   100000
#define N_ITEM   50000
#define N_NODES_ (N_USER + N_ITEM)   // 150000
#define NNZ_     4800000
#define EMB      64
#define N_LAYERS 3
#define BATCH_   16384
#define EPS_     1e-12f
#define NEG_SLOPE 0.2f

// ---------------- scratch (device globals: allocation-free rule) -------------
__device__ float  g_ego  [N_NODES_ * EMB];      // fp32 layer input (unnormalized)
__device__ __half g_ego_h[N_NODES_ * EMB];      // fp16 shadow for spmm gathers
__device__ float  g_side [N_NODES_ * EMB];      // A_hat @ ego (written whole by CSR spmm)
__device__ float  g_all  [N_NODES_ * 4 * EMB];  // concat of 4 embedding blocks
// CSR build scratch.  g_row_cnt is zero-initialized at module load and
// re-zeroed by scan_kernel after it is consumed -> every replay sees zeros.
__device__ int   g_row_cnt[N_NODES_];
__device__ int   g_row_cur[N_NODES_];           // seeded with row offsets by scan
__device__ int   g_row_off[N_NODES_ + 1];
__device__ int2  g_edge_s [NNZ_];               // packed (col, val_bits), row-sorted

// ------- init: ego = concat(user_emb, item_emb) (fp32 + fp16 shadow) ---------
// Also fuses the degree count (first NNZ/4 threads handle one edge-quad each).
__global__ void init_kernel(const float* __restrict__ ue, const float* __restrict__ ie,
                            const int* __restrict__ rows) {
    int idx = blockIdx.x * blockDim.x + threadIdx.x;      // float4 / half4 index
    const int total = N_NODES_ * EMB / 4;                 // 2.4M
    if (idx < total) {
        int node = idx >> 4;
        int c4   = idx & 15;
        float4 v;
        if (node < N_USER) v = __ldg((const float4*)ue + node * 16 + c4);
        else               v = __ldg((const float4*)ie + (node - N_USER) * 16 + c4);
        ((float4*)g_ego)[idx] = v;
        ((float4*)g_all)[node * 64 + c4] = v;
        __half2 h0 = __floats2half2_rn(v.x, v.y);
        __half2 h1 = __floats2half2_rn(v.z, v.w);
        uint2 pk;
        pk.x = *(unsigned*)&h0;
        pk.y = *(unsigned*)&h1;
        ((uint2*)g_ego_h)[idx] = pk;
    }
    if (idx < NNZ_ / 4) {             // fused degree count (cnt pre-zeroed)
        int4 r4 = __ldg((const int4*)rows + idx);
        atomicAdd(&g_row_cnt[r4.x], 1);
        atomicAdd(&g_row_cnt[r4.y], 1);
        atomicAdd(&g_row_cnt[r4.z], 1);
        atomicAdd(&g_row_cnt[r4.w], 1);
    }
}

// ---------------- CSR build: coalesced wave-scan (single block, 1024 thr) ----
// 147 waves of 1024 CONSECUTIVE elements: every load/store is coalesced
// (the old per-thread-chunk layout cost 32 wavefronts per access on one SM).
// Shuffle Kogge-Stone within warps, smem scan across warps, carried total.
// Zeroes g_row_cnt for the next replay and seeds g_row_cur with offsets.
__global__ void scan_kernel() {
    __shared__ int warp_sums[32];
    const int NWAVES = (N_NODES_ + 1023) / 1024;   // 147
    int t    = threadIdx.x;
    int lane = t & 31;
    int wid  = t >> 5;
    int carry = 0;
    for (int w = 0; w < NWAVES; w++) {
        int idx = w * 1024 + t;
        int c = 0;
        if (idx < N_NODES_) {
            c = g_row_cnt[idx];
            g_row_cnt[idx] = 0;     // reset for next replay
        }
        int x = c;                  // inclusive warp scan
#pragma unroll
        for (int off = 1; off < 32; off <<= 1) {
            int y = __shfl_up_sync(0xffffffffu, x, off);
            if (lane >= off) x += y;
        }
        if (lane == 31) warp_sums[wid] = x;
        __syncthreads();
        if (wid == 0) {             // scan the 32 warp totals
            int wv = warp_sums[lane];
#pragma unroll
            for (int off = 1; off < 32; off <<= 1) {
                int y = __shfl_up_sync(0xffffffffu, wv, off);
                if (lane >= off) wv += y;
            }
            warp_sums[lane] = wv;   // inclusive over warps
        }
        __syncthreads();
        int warp_excl = (wid > 0) ? warp_sums[wid - 1] : 0;
        int excl = carry + warp_excl + (x - c);
        if (idx < N_NODES_) {
            g_row_off[idx] = excl;
            g_row_cur[idx] = excl;  // cursor starts at row start
        }
        carry += warp_sums[31];     // wave total
        __syncthreads();            // protect warp_sums before next wave
    }
    if (t == 0) g_row_off[N_NODES_] = carry;   // total = NNZ
}

// ---------------- CSR build: scatter edges ------------------------------------
// 8 independent atomic->store chains per thread; position comes straight from
// the cursor atomic; one packed int2 store per edge.
__global__ void scatter_kernel(const int* __restrict__ rows,
                               const int* __restrict__ cols,
                               const int* __restrict__ vals) {
    int q = blockIdx.x * blockDim.x + threadIdx.x;   // octet id
    if (q >= NNZ_ / 8) return;
    int4 ra = __ldg((const int4*)rows + q * 2);
    int4 rb = __ldg((const int4*)rows + q * 2 + 1);
    int4 ca = __ldg((const int4*)cols + q * 2);
    int4 cb = __ldg((const int4*)cols + q * 2 + 1);
    int4 va = __ldg((const int4*)vals + q * 2);      // val bits
    int4 vb = __ldg((const int4*)vals + q * 2 + 1);
    int r[8] = {ra.x, ra.y, ra.z, ra.w, rb.x, rb.y, rb.z, rb.w};
    int c[8] = {ca.x, ca.y, ca.z, ca.w, cb.x, cb.y, cb.z, cb.w};
    int v[8] = {va.x, va.y, va.z, va.w, vb.x, vb.y, vb.z, vb.w};
    int p[8];
#pragma unroll
    for (int u = 0; u < 8; u++) p[u] = atomicAdd(&g_row_cur[r[u]], 1);
#pragma unroll
    for (int u = 0; u < 8; u++) g_edge_s[p[u]] = make_int2(c[u], v[u]);
}

// ---------------- CSR SpMM: fp16 gather, fp32 accumulate (measured 63us) ------
// 16 lanes per row; packed int2 edge loads; 4-edge unroll (MLP=4, low regs).
__global__ void spmm_csr_kernel() {
    int t = blockIdx.x * blockDim.x + threadIdx.x;
    int r = t >> 4;                 // row id (grid sized exactly)
    int l = t & 15;
    int beg = __ldg(&g_row_off[r]);
    int end = __ldg(&g_row_off[r + 1]);
    float4 acc = make_float4(0.f, 0.f, 0.f, 0.f);
    int e = beg;
    for (; e + 4 <= end; e += 4) {
        int2 E0 = __ldg(&g_edge_s[e + 0]);
        int2 E1 = __ldg(&g_edge_s[e + 1]);
        int2 E2 = __ldg(&g_edge_s[e + 2]);
        int2 E3 = __ldg(&g_edge_s[e + 3]);
        uint2 w0 = __ldg((const uint2*)g_ego_h + E0.x * 16 + l);
        uint2 w1 = __ldg((const uint2*)g_ego_h + E1.x * 16 + l);
        uint2 w2 = __ldg((const uint2*)g_ego_h + E2.x * 16 + l);
        uint2 w3 = __ldg((const uint2*)g_ego_h + E3.x * 16 + l);
        float v0 = __int_as_float(E0.y);
        float v1 = __int_as_float(E1.y);
        float v2 = __int_as_float(E2.y);
        float v3 = __int_as_float(E3.y);
        float2 a0 = __half22float2(*(const __half2*)&w0.x);
        float2 b0 = __half22float2(*(const __half2*)&w0.y);
        float2 a1 = __half22float2(*(const __half2*)&w1.x);
        float2 b1 = __half22float2(*(const __half2*)&w1.y);
        float2 a2 = __half22float2(*(const __half2*)&w2.x);
        float2 b2 = __half22float2(*(const __half2*)&w2.y);
        float2 a3 = __half22float2(*(const __half2*)&w3.x);
        float2 b3 = __half22float2(*(const __half2*)&w3.y);
        acc.x += a0.x * v0 + a1.x * v1 + a2.x * v2 + a3.x * v3;
        acc.y += a0.y * v0 + a1.y * v1 + a2.y * v2 + a3.y * v3;
        acc.z += b0.x * v0 + b1.x * v1 + b2.x * v2 + b3.x * v3;
        acc.w += b0.y * v0 + b1.y * v1 + b2.y * v2 + b3.y * v3;
    }
    for (; e < end; e++) {
        int2 E = __ldg(&g_edge_s[e]);
        float v = __int_as_float(E.y);
        uint2 w = __ldg((const uint2*)g_ego_h + E.x * 16 + l);
        float2 a = __half22float2(*(const __half2*)&w.x);
        float2 b = __half22float2(*(const __half2*)&w.y);
        acc.x += a.x * v; acc.y += a.y * v; acc.z += b.x * v; acc.w += b.y * v;
    }
    ((float4*)g_side)[r * 16 + l] = acc;
}

// ---------------- fused dense transform + leaky_relu + L2-normalize ----------
// R1-measured structure (92us). Epilogue refreshes the fp16 shadow of ego
// for the next layer's spmm (layers 0,1 only).
__global__ void transform_kernel(const float* __restrict__ Wgc,
                                 const float* __restrict__ bgc,
                                 const float* __restrict__ Wbi,
                                 const float* __restrict__ bbi,
                                 int layer) {
    extern __shared__ float sh[];
    float* Ssh = sh;                    // [64][65]
    float* Psh = Ssh + 64 * 65;         // [64][65]
    float* Wg  = Psh + 64 * 65;         // [64][64]
    float* Wb  = Wg  + 64 * 64;         // [64][64]
    float* bs  = Wb  + 64 * 64;         // [64]

    const int tid = threadIdx.x;
    const int rowBase = blockIdx.x * 64;

    for (int i = tid; i < 1024; i += 256) {
        ((float4*)Wg)[i] = __ldg((const float4*)Wgc + i);
        ((float4*)Wb)[i] = __ldg((const float4*)Wbi + i);
    }
    if (tid < 64) bs[tid] = __ldg(bgc + tid) + __ldg(bbi + tid);

    for (int i = tid; i < 1024; i += 256) {
        int r  = i >> 4;
        int c4 = i & 15;
        int gr = rowBase + r;
        float4 s = make_float4(0.f, 0.f, 0.f, 0.f);
        float4 e = make_float4(0.f, 0.f, 0.f, 0.f);
        if (gr < N_NODES_) {
            s = ((const float4*)g_side)[gr * 16 + c4];
            e = ((const float4*)g_ego )[gr * 16 + c4];
        }
        float* sp = Ssh + r * 65 + c4 * 4;
        sp[0] = s.x; sp[1] = s.y; sp[2] = s.z; sp[3] = s.w;
        float* pp = Psh + r * 65 + c4 * 4;
        pp[0] = e.x * s.x; pp[1] = e.y * s.y; pp[2] = e.z * s.z; pp[3] = e.w * s.w;
    }
    __syncthreads();

    const int tx = tid & 15;
    const int ty = tid >> 4;
    float acc[4][4];
#pragma unroll
    for (int i = 0; i < 4; i++)
#pragma unroll
        for (int j = 0; j < 4; j++) acc[i][j] = 0.f;

#pragma unroll 8
    for (int k = 0; k < 64; k++) {
        float4 bg = *(const float4*)&Wg[k * 64 + tx * 4];
        float4 bb = *(const float4*)&Wb[k * 64 + tx * 4];
        float as[4], ap[4];
#pragma unroll
        for (int i = 0; i < 4; i++) {
            as[i] = Ssh[(ty * 4 + i) * 65 + k];
            ap[i] = Psh[(ty * 4 + i) * 65 + k];
        }
#pragma unroll
        for (int i = 0; i < 4; i++) {
            acc[i][0] += as[i] * bg.x + ap[i] * bb.x;
            acc[i][1] += as[i] * bg.y + ap[i] * bb.y;
            acc[i][2] += as[i] * bg.z + ap[i] * bb.z;
            acc[i][3] += as[i] * bg.w + ap[i] * bb.w;
        }
    }

    const int colBase = tx * 4;
    float v[4][4];
    float sq[4];
#pragma unroll
    for (int i = 0; i < 4; i++) {
        float x0 = acc[i][0] + bs[colBase + 0];
        float x1 = acc[i][1] + bs[colBase + 1];
        float x2 = acc[i][2] + bs[colBase + 2];
        float x3 = acc[i][3] + bs[colBase + 3];
        x0 = fmaxf(x0, NEG_SLOPE * x0);
        x1 = fmaxf(x1, NEG_SLOPE * x1);
        x2 = fmaxf(x2, NEG_SLOPE * x2);
        x3 = fmaxf(x3, NEG_SLOPE * x3);
        v[i][0] = x0; v[i][1] = x1; v[i][2] = x2; v[i][3] = x3;
        float s = x0 * x0 + x1 * x1 + x2 * x2 + x3 * x3;
#pragma unroll
        for (int off = 1; off < 16; off <<= 1)
            s += __shfl_xor_sync(0xffffffffu, s, off);
        sq[i] = s;
    }

#pragma unroll
    for (int i = 0; i < 4; i++) {
        int gr = rowBase + ty * 4 + i;
        if (gr >= N_NODES_) continue;
        float inv = 1.0f / fmaxf(sqrtf(sq[i]), EPS_);
        float4 raw = make_float4(v[i][0], v[i][1], v[i][2], v[i][3]);
        float4 nrm = make_float4(v[i][0] * inv, v[i][1] * inv, v[i][2] * inv, v[i][3] * inv);
        *(float4*)&g_ego[(size_t)gr * EMB + colBase] = raw;
        *(float4*)&g_all[(size_t)gr * 256 + (layer + 1) * 64 + colBase] = nrm;
        if (layer < N_LAYERS - 1) {
            __half2 h0 = __floats2half2_rn(raw.x, raw.y);
            __half2 h1 = __floats2half2_rn(raw.z, raw.w);
            uint2 pk;
            pk.x = *(unsigned*)&h0;
            pk.y = *(unsigned*)&h1;
            *(uint2*)&g_ego_h[(size_t)gr * EMB + colBase] = pk;
        }
    }
}

// ---------------- GMF head: sigmoid((u*i)@W_out + b_out) ---------------------
__global__ void head_kernel(const int* __restrict__ uidx,
                            const int* __restrict__ iidx,
                            const float* __restrict__ Wout,
                            const float* __restrict__ bout,
                            float* __restrict__ out) {
    int gw = (blockIdx.x * blockDim.x + threadIdx.x) >> 5;
    if (gw >= BATCH_) return;
    int lane = threadIdx.x & 31;
    int u  = __ldg(&uidx[gw]);
    int it = __ldg(&iidx[gw]) + N_USER;
    const float4* ur = (const float4*)(g_all + (size_t)u  * 256);
    const float4* ir = (const float4*)(g_all + (size_t)it * 256);
    const float4* w4 = (const float4*)Wout;
    float acc = 0.f;
#pragma unroll
    for (int q = 0; q < 2; q++) {
        int c = lane + q * 32;
        float4 a = ur[c];
        float4 b = ir[c];
        float4 w = __ldg(&w4[c]);
        acc += a.x * b.x * w.x + a.y * b.y * w.y + a.z * b.z * w.z + a.w * b.w * w.w;
    }
#pragma unroll
    for (int off = 16; off; off >>= 1)
        acc += __shfl_xor_sync(0xffffffffu, acc, off);
    if (lane == 0) {
        float z = acc + __ldg(bout);
        out[gw] = 1.0f / (1.0f + expf(-z));
    }
}

// ---------------- launch ------------------------------------------------------
extern "C" void kernel_launch(void* const* d_in, const int* in_sizes, int n_in,
                              void* d_out, int out_size) {
    const int*   user_idx = (const int*)  d_in[0];
    const int*   item_idx = (const int*)  d_in[1];
    const int*   adj_rows = (const int*)  d_in[2];
    const int*   adj_cols = (const int*)  d_in[3];
    const int*   adj_vals = (const int*)  d_in[4];   // raw bits for scatter
    const float* user_emb = (const float*)d_in[5];
    const float* item_emb = (const float*)d_in[6];
    const float* W_gc     = (const float*)d_in[7];
    const float* b_gc     = (const float*)d_in[8];
    const float* W_bi     = (const float*)d_in[9];
    const float* b_bi     = (const float*)d_in[10];
    const float* W_out    = (const float*)d_in[11];
    const float* b_out    = (const float*)d_in[12];
    float* out = (float*)d_out;

    const int smem = (64 * 65 * 2 + 64 * 64 * 2 + 64) * (int)sizeof(float);  // 66304 B
    cudaFuncSetAttribute(transform_kernel,
                         cudaFuncAttributeMaxDynamicSharedMemorySize, smem);

    const int vec_blocks = (N_NODES_ * EMB / 4) / 256;   // 9375 (covers NNZ/4=1.2M too)
    init_kernel<<<vec_blocks, 256>>>(user_emb, item_emb, adj_rows);

    scan_kernel<<<1, 1024>>>();
    scatter_kernel<<<(NNZ_ / 8 + 255) / 256, 256>>>(adj_rows, adj_cols, adj_vals);

    const int spmm_blocks = (N_NODES_ * 16) / 256;       // 9375 exactly
    const int tile_blocks = (N_NODES_ + 63) / 64;        // 2344

    for (int l = 0; l < N_LAYERS; l++) {
        spmm_csr_kernel<<<spmm_blocks, 256>>>();
        transform_kernel<<<tile_blocks, 256, smem>>>(W_gc + l * EMB * EMB,
                                                     b_gc + l * EMB,
                                                     W_bi + l * EMB * EMB,
                                                     b_bi + l * EMB,
                                                     l);
    }

    head_kernel<<<(BATCH_ * 32) / 256, 256>>>(user_idx, item_idx, W_out, b_out, out);
}

// round 12
// speedup vs baseline: 1.5920x; 1.2672x over previous
#include <cuda_runtime.h>
#include <cuda_fp16.h>
#include <mma.h>
#include <math.h>

using namespace nvcuda;

#define N_USER   100000
#define N_ITEM   50000
#define N_NODES_ (N_USER + N_ITEM)   // 150000
#define NNZ_     4800000
#define EMB      64
#define N_LAYERS 3
#define BATCH_   16384
#define EPS_     1e-12f
#define NEG_SLOPE 0.2f

// shared-memory layout constants for transform (bytes)
#define A_LD   136                    // halves per row of A=[S|P], 272B (16B-mult)
#define B_LD   72                     // halves per row of B=[Wg;Wb], 144B
#define C_LD   72                     // floats per row of C, 288B
#define SH_A   0
#define SH_B   (64 * A_LD * 2)                    // 17408
#define SH_C   (SH_B + 128 * B_LD * 2)            // 35840
#define SH_BS  (SH_C + 64 * C_LD * 4)             // 54272
#define SH_TOT (SH_BS + 64 * 4)                   // 54528

// ---------------- scratch (device globals: allocation-free rule) -------------
__device__ float  g_ego  [N_NODES_ * EMB];      // fp32 layer input (unnormalized)
__device__ __half g_ego_h[N_NODES_ * EMB];      // fp16 shadow for spmm gathers
__device__ float  g_side [N_NODES_ * EMB];      // A_hat @ ego (written whole by CSR spmm)
__device__ float  g_all  [N_NODES_ * 4 * EMB];  // concat of 4 embedding blocks
// CSR build scratch.  g_row_cnt is zero-initialized at module load and
// re-zeroed by scan_kernel after it is consumed -> every replay sees zeros.
__device__ int   g_row_cnt[N_NODES_];
__device__ int   g_row_cur[N_NODES_];           // seeded with row offsets by scan
__device__ int   g_row_off[N_NODES_ + 1];
__device__ int2  g_edge_s [NNZ_];               // packed (col, val_bits), row-sorted

// ------- init: ego = concat(user_emb, item_emb) (fp32 + fp16 shadow) ---------
// Also fuses the degree count (first NNZ/4 threads handle one edge-quad each).
__global__ void init_kernel(const float* __restrict__ ue, const float* __restrict__ ie,
                            const int* __restrict__ rows) {
    int idx = blockIdx.x * blockDim.x + threadIdx.x;      // float4 / half4 index
    const int total = N_NODES_ * EMB / 4;                 // 2.4M
    if (idx < total) {
        int node = idx >> 4;
        int c4   = idx & 15;
        float4 v;
        if (node < N_USER) v = __ldg((const float4*)ue + node * 16 + c4);
        else               v = __ldg((const float4*)ie + (node - N_USER) * 16 + c4);
        ((float4*)g_ego)[idx] = v;
        ((float4*)g_all)[node * 64 + c4] = v;
        __half2 h0 = __floats2half2_rn(v.x, v.y);
        __half2 h1 = __floats2half2_rn(v.z, v.w);
        uint2 pk;
        pk.x = *(unsigned*)&h0;
        pk.y = *(unsigned*)&h1;
        ((uint2*)g_ego_h)[idx] = pk;
    }
    if (idx < NNZ_ / 4) {             // fused degree count (cnt pre-zeroed)
        int4 r4 = __ldg((const int4*)rows + idx);
        atomicAdd(&g_row_cnt[r4.x], 1);
        atomicAdd(&g_row_cnt[r4.y], 1);
        atomicAdd(&g_row_cnt[r4.z], 1);
        atomicAdd(&g_row_cnt[r4.w], 1);
    }
}

// ---------------- CSR build: coalesced wave-scan (single block, 1024 thr) ----
__global__ void scan_kernel() {
    __shared__ int warp_sums[32];
    const int NWAVES = (N_NODES_ + 1023) / 1024;   // 147
    int t    = threadIdx.x;
    int lane = t & 31;
    int wid  = t >> 5;
    int carry = 0;
    for (int w = 0; w < NWAVES; w++) {
        int idx = w * 1024 + t;
        int c = 0;
        if (idx < N_NODES_) {
            c = g_row_cnt[idx];
            g_row_cnt[idx] = 0;     // reset for next replay
        }
        int x = c;                  // inclusive warp scan
#pragma unroll
        for (int off = 1; off < 32; off <<= 1) {
            int y = __shfl_up_sync(0xffffffffu, x, off);
            if (lane >= off) x += y;
        }
        if (lane == 31) warp_sums[wid] = x;
        __syncthreads();
        if (wid == 0) {             // scan the 32 warp totals
            int wv = warp_sums[lane];
#pragma unroll
            for (int off = 1; off < 32; off <<= 1) {
                int y = __shfl_up_sync(0xffffffffu, wv, off);
                if (lane >= off) wv += y;
            }
            warp_sums[lane] = wv;   // inclusive over warps
        }
        __syncthreads();
        int warp_excl = (wid > 0) ? warp_sums[wid - 1] : 0;
        int excl = carry + warp_excl + (x - c);
        if (idx < N_NODES_) {
            g_row_off[idx] = excl;
            g_row_cur[idx] = excl;  // cursor starts at row start
        }
        carry += warp_sums[31];     // wave total
        __syncthreads();            // protect warp_sums before next wave
    }
    if (t == 0) g_row_off[N_NODES_] = carry;   // total = NNZ
}

// ---------------- CSR build: scatter edges ------------------------------------
__global__ void scatter_kernel(const int* __restrict__ rows,
                               const int* __restrict__ cols,
                               const int* __restrict__ vals) {
    int q = blockIdx.x * blockDim.x + threadIdx.x;   // octet id
    if (q >= NNZ_ / 8) return;
    int4 ra = __ldg((const int4*)rows + q * 2);
    int4 rb = __ldg((const int4*)rows + q * 2 + 1);
    int4 ca = __ldg((const int4*)cols + q * 2);
    int4 cb = __ldg((const int4*)cols + q * 2 + 1);
    int4 va = __ldg((const int4*)vals + q * 2);      // val bits
    int4 vb = __ldg((const int4*)vals + q * 2 + 1);
    int r[8] = {ra.x, ra.y, ra.z, ra.w, rb.x, rb.y, rb.z, rb.w};
    int c[8] = {ca.x, ca.y, ca.z, ca.w, cb.x, cb.y, cb.z, cb.w};
    int v[8] = {va.x, va.y, va.z, va.w, vb.x, vb.y, vb.z, vb.w};
    int p[8];
#pragma unroll
    for (int u = 0; u < 8; u++) p[u] = atomicAdd(&g_row_cur[r[u]], 1);
#pragma unroll
    for (int u = 0; u < 8; u++) g_edge_s[p[u]] = make_int2(c[u], v[u]);
}

// ---------------- CSR SpMM: fp16 gather, fp32 accumulate (measured 63us) ------
__global__ void spmm_csr_kernel() {
    int t = blockIdx.x * blockDim.x + threadIdx.x;
    int r = t >> 4;                 // row id (grid sized exactly)
    int l = t & 15;
    int beg = __ldg(&g_row_off[r]);
    int end = __ldg(&g_row_off[r + 1]);
    float4 acc = make_float4(0.f, 0.f, 0.f, 0.f);
    int e = beg;
    for (; e + 4 <= end; e += 4) {
        int2 E0 = __ldg(&g_edge_s[e + 0]);
        int2 E1 = __ldg(&g_edge_s[e + 1]);
        int2 E2 = __ldg(&g_edge_s[e + 2]);
        int2 E3 = __ldg(&g_edge_s[e + 3]);
        uint2 w0 = __ldg((const uint2*)g_ego_h + E0.x * 16 + l);
        uint2 w1 = __ldg((const uint2*)g_ego_h + E1.x * 16 + l);
        uint2 w2 = __ldg((const uint2*)g_ego_h + E2.x * 16 + l);
        uint2 w3 = __ldg((const uint2*)g_ego_h + E3.x * 16 + l);
        float v0 = __int_as_float(E0.y);
        float v1 = __int_as_float(E1.y);
        float v2 = __int_as_float(E2.y);
        float v3 = __int_as_float(E3.y);
        float2 a0 = __half22float2(*(const __half2*)&w0.x);
        float2 b0 = __half22float2(*(const __half2*)&w0.y);
        float2 a1 = __half22float2(*(const __half2*)&w1.x);
        float2 b1 = __half22float2(*(const __half2*)&w1.y);
        float2 a2 = __half22float2(*(const __half2*)&w2.x);
        float2 b2 = __half22float2(*(const __half2*)&w2.y);
        float2 a3 = __half22float2(*(const __half2*)&w3.x);
        float2 b3 = __half22float2(*(const __half2*)&w3.y);
        acc.x += a0.x * v0 + a1.x * v1 + a2.x * v2 + a3.x * v3;
        acc.y += a0.y * v0 + a1.y * v1 + a2.y * v2 + a3.y * v3;
        acc.z += b0.x * v0 + b1.x * v1 + b2.x * v2 + b3.x * v3;
        acc.w += b0.y * v0 + b1.y * v1 + b2.y * v2 + b3.y * v3;
    }
    for (; e < end; e++) {
        int2 E = __ldg(&g_edge_s[e]);
        float v = __int_as_float(E.y);
        uint2 w = __ldg((const uint2*)g_ego_h + E.x * 16 + l);
        float2 a = __half22float2(*(const __half2*)&w.x);
        float2 b = __half22float2(*(const __half2*)&w.y);
        acc.x += a.x * v; acc.y += a.y * v; acc.z += b.x * v; acc.w += b.y * v;
    }
    ((float4*)g_side)[r * 16 + l] = acc;
}

// ---------------- tensor-core transform + leaky_relu + L2-normalize ----------
// out = leaky([S|P](64x128) @ [Wg;Wb](128x64) + b), then row-normalize.
// fp16 wmma (HMMA) with fp32 accumulators. 256 threads, 64-row tile.
__global__ void transform_kernel(const float* __restrict__ Wgc,
                                 const float* __restrict__ bgc,
                                 const float* __restrict__ Wbi,
                                 const float* __restrict__ bbi,
                                 int layer) {
    extern __shared__ char sh[];
    __half* A_h = (__half*)(sh + SH_A);   // [64][A_LD]
    __half* B_h = (__half*)(sh + SH_B);   // [128][B_LD]
    float*  C_f = (float*) (sh + SH_C);   // [64][C_LD]
    float*  bs  = (float*) (sh + SH_BS);  // [64]

    const int tid = threadIdx.x;
    const int rowBase = blockIdx.x * 64;

    // stage B = [Wg; Wb] as fp16 (1024 float4 loads each, coalesced)
    for (int i = tid; i < 1024; i += 256) {
        int k = i >> 4;               // 0..63
        int n4 = i & 15;              // float4 col group
        float4 wg = __ldg((const float4*)Wgc + i);
        float4 wb = __ldg((const float4*)Wbi + i);
        __half2* dg = (__half2*)&B_h[k * B_LD + n4 * 4];
        dg[0] = __floats2half2_rn(wg.x, wg.y);
        dg[1] = __floats2half2_rn(wg.z, wg.w);
        __half2* db = (__half2*)&B_h[(64 + k) * B_LD + n4 * 4];
        db[0] = __floats2half2_rn(wb.x, wb.y);
        db[1] = __floats2half2_rn(wb.z, wb.w);
    }
    if (tid < 64) bs[tid] = __ldg(bgc + tid) + __ldg(bbi + tid);

    // stage A = [S | ego*S] as fp16 (coalesced global reads)
    for (int i = tid; i < 1024; i += 256) {
        int r  = i >> 4;
        int c4 = i & 15;
        int gr = rowBase + r;
        float4 s = make_float4(0.f, 0.f, 0.f, 0.f);
        float4 e = make_float4(0.f, 0.f, 0.f, 0.f);
        if (gr < N_NODES_) {
            s = ((const float4*)g_side)[gr * 16 + c4];
            e = ((const float4*)g_ego )[gr * 16 + c4];
        }
        __half2* ds = (__half2*)&A_h[r * A_LD + c4 * 4];
        ds[0] = __floats2half2_rn(s.x, s.y);
        ds[1] = __floats2half2_rn(s.z, s.w);
        __half2* dp = (__half2*)&A_h[r * A_LD + 64 + c4 * 4];
        dp[0] = __floats2half2_rn(e.x * s.x, e.y * s.y);
        dp[1] = __floats2half2_rn(e.z * s.z, e.w * s.w);
    }
    __syncthreads();

    // wmma: 8 warps, each owns one 16-row tile slice x 2 col tiles
    {
        int w = tid >> 5;             // 0..7
        int rt = w >> 1;              // row tile 0..3
        int ct = (w & 1) * 2;         // col tiles ct, ct+1
        wmma::fragment<wmma::accumulator, 16, 16, 16, float> c0, c1;
        wmma::fill_fragment(c0, 0.0f);
        wmma::fill_fragment(c1, 0.0f);
#pragma unroll
        for (int k = 0; k < 8; k++) {
            wmma::fragment<wmma::matrix_a, 16, 16, 16, __half, wmma::row_major> a;
            wmma::fragment<wmma::matrix_b, 16, 16, 16, __half, wmma::row_major> b0, b1;
            wmma::load_matrix_sync(a, &A_h[rt * 16 * A_LD + k * 16], A_LD);
            wmma::load_matrix_sync(b0, &B_h[k * 16 * B_LD + ct * 16], B_LD);
            wmma::load_matrix_sync(b1, &B_h[k * 16 * B_LD + (ct + 1) * 16], B_LD);
            wmma::mma_sync(c0, a, b0, c0);
            wmma::mma_sync(c1, a, b1, c1);
        }
        wmma::store_matrix_sync(&C_f[rt * 16 * C_LD + ct * 16], c0, C_LD, wmma::mem_row_major);
        wmma::store_matrix_sync(&C_f[rt * 16 * C_LD + (ct + 1) * 16], c1, C_LD, wmma::mem_row_major);
    }
    __syncthreads();

    // epilogue: bias + leaky, row-norm across 16 tx lanes, write back
    const int tx = tid & 15;
    const int ty = tid >> 4;
    const int colBase = tx * 4;
    float b0 = bs[colBase + 0], b1 = bs[colBase + 1];
    float b2 = bs[colBase + 2], b3 = bs[colBase + 3];
#pragma unroll
    for (int i = 0; i < 4; i++) {
        int r = ty * 4 + i;
        float4 xc = *(const float4*)&C_f[r * C_LD + colBase];
        float x0 = xc.x + b0;
        float x1 = xc.y + b1;
        float x2 = xc.z + b2;
        float x3 = xc.w + b3;
        x0 = fmaxf(x0, NEG_SLOPE * x0);
        x1 = fmaxf(x1, NEG_SLOPE * x1);
        x2 = fmaxf(x2, NEG_SLOPE * x2);
        x3 = fmaxf(x3, NEG_SLOPE * x3);
        float sq = x0 * x0 + x1 * x1 + x2 * x2 + x3 * x3;
#pragma unroll
        for (int off = 1; off < 16; off <<= 1)
            sq += __shfl_xor_sync(0xffffffffu, sq, off);
        int gr = rowBase + r;
        if (gr < N_NODES_) {
            float inv = 1.0f / fmaxf(sqrtf(sq), EPS_);
            float4 raw = make_float4(x0, x1, x2, x3);
            *(float4*)&g_ego[(size_t)gr * EMB + colBase] = raw;
            *(float4*)&g_all[(size_t)gr * 256 + (layer + 1) * 64 + colBase] =
                make_float4(x0 * inv, x1 * inv, x2 * inv, x3 * inv);
            if (layer < N_LAYERS - 1) {
                __half2 h0 = __floats2half2_rn(x0, x1);
                __half2 h1 = __floats2half2_rn(x2, x3);
                uint2 pk;
                pk.x = *(unsigned*)&h0;
                pk.y = *(unsigned*)&h1;
                *(uint2*)&g_ego_h[(size_t)gr * EMB + colBase] = pk;
            }
        }
    }
}

// ---------------- GMF head: sigmoid((u*i)@W_out + b_out) ---------------------
__global__ void head_kernel(const int* __restrict__ uidx,
                            const int* __restrict__ iidx,
                            const float* __restrict__ Wout,
                            const float* __restrict__ bout,
                            float* __restrict__ out) {
    int gw = (blockIdx.x * blockDim.x + threadIdx.x) >> 5;
    if (gw >= BATCH_) return;
    int lane = threadIdx.x & 31;
    int u  = __ldg(&uidx[gw]);
    int it = __ldg(&iidx[gw]) + N_USER;
    const float4* ur = (const float4*)(g_all + (size_t)u  * 256);
    const float4* ir = (const float4*)(g_all + (size_t)it * 256);
    const float4* w4 = (const float4*)Wout;
    float acc = 0.f;
#pragma unroll
    for (int q = 0; q < 2; q++) {
        int c = lane + q * 32;
        float4 a = ur[c];
        float4 b = ir[c];
        float4 w = __ldg(&w4[c]);
        acc += a.x * b.x * w.x + a.y * b.y * w.y + a.z * b.z * w.z + a.w * b.w * w.w;
    }
#pragma unroll
    for (int off = 16; off; off >>= 1)
        acc += __shfl_xor_sync(0xffffffffu, acc, off);
    if (lane == 0) {
        float z = acc + __ldg(bout);
        out[gw] = 1.0f / (1.0f + expf(-z));
    }
}

// ---------------- launch ------------------------------------------------------
extern "C" void kernel_launch(void* const* d_in, const int* in_sizes, int n_in,
                              void* d_out, int out_size) {
    const int*   user_idx = (const int*)  d_in[0];
    const int*   item_idx = (const int*)  d_in[1];
    const int*   adj_rows = (const int*)  d_in[2];
    const int*   adj_cols = (const int*)  d_in[3];
    const int*   adj_vals = (const int*)  d_in[4];   // raw bits for scatter
    const float* user_emb = (const float*)d_in[5];
    const float* item_emb = (const float*)d_in[6];
    const float* W_gc     = (const float*)d_in[7];
    const float* b_gc     = (const float*)d_in[8];
    const float* W_bi     = (const float*)d_in[9];
    const float* b_bi     = (const float*)d_in[10];
    const float* W_out    = (const float*)d_in[11];
    const float* b_out    = (const float*)d_in[12];
    float* out = (float*)d_out;

    cudaFuncSetAttribute(transform_kernel,
                         cudaFuncAttributeMaxDynamicSharedMemorySize, SH_TOT);

    const int vec_blocks = (N_NODES_ * EMB / 4) / 256;   // 9375 (covers NNZ/4=1.2M too)
    init_kernel<<<vec_blocks, 256>>>(user_emb, item_emb, adj_rows);

    scan_kernel<<<1, 1024>>>();
    scatter_kernel<<<(NNZ_ / 8 + 255) / 256, 256>>>(adj_rows, adj_cols, adj_vals);

    const int spmm_blocks = (N_NODES_ * 16) / 256;       // 9375 exactly
    const int tile_blocks = (N_NODES_ + 63) / 64;        // 2344

    for (int l = 0; l < N_LAYERS; l++) {
        spmm_csr_kernel<<<spmm_blocks, 256>>>();
        transform_kernel<<<tile_blocks, 256, SH_TOT>>>(W_gc + l * EMB * EMB,
                                                       b_gc + l * EMB,
                                                       W_bi + l * EMB * EMB,
                                                       b_bi + l * EMB,
                                                       l);
    }

    head_kernel<<<(BATCH_ * 32) / 256, 256>>>(user_idx, item_idx, W_out, b_out, out);
}

// round 13
// speedup vs baseline: 1.8597x; 1.1681x over previous
#include <cuda_runtime.h>
#include <cuda_fp16.h>
#include <mma.h>
#include <math.h>

using namespace nvcuda;

#define N_USER   100000
#define N_ITEM   50000
#define N_NODES_ (N_USER + N_ITEM)   // 150000
#define NNZ_     4800000
#define EMB      64
#define N_LAYERS 3
#define BATCH_   16384
#define EPS_     1e-12f
#define NEG_SLOPE 0.2f

// shared-memory layout constants for transform (bytes)
#define A_LD   136                    // halves per row of A=[S|P], 272B
#define B_LD   72                     // halves per row of B=[Wg;Wb], 144B
#define C_LD   72                     // floats per row of C, 288B
#define SH_A   0
#define SH_B   (64 * A_LD * 2)                    // 17408
#define SH_C   (SH_B + 128 * B_LD * 2)            // 35840
#define SH_BS  (SH_C + 64 * C_LD * 4)             // 54272
#define SH_TOT (SH_BS + 64 * 4)                   // 54528

// ---------------- scratch (device globals: allocation-free rule) -------------
__device__ __half g_ego_h [N_NODES_ * EMB];     // fp16 ego (only node state needed)
__device__ __half g_side_h[N_NODES_ * EMB];     // fp16 A_hat @ ego
__device__ float  g_all   [N_NODES_ * 4 * EMB]; // concat of 4 embedding blocks
// CSR build scratch.  g_row_cnt is zero-initialized at module load and
// re-zeroed by scan_kernel after it is consumed -> every replay sees zeros.
__device__ int   g_row_cnt[N_NODES_];
__device__ int   g_row_cur[N_NODES_];           // seeded with row offsets by scan
__device__ int   g_row_off[N_NODES_ + 1];
__device__ int2  g_edge_s [NNZ_];               // packed (col, val_bits), row-sorted

// ------- init: ego_h = fp16(concat(user_emb, item_emb)); all[:,0:64] = fp32 --
// Also fuses the degree count (first NNZ/4 threads handle one edge-quad each).
__global__ void init_kernel(const float* __restrict__ ue, const float* __restrict__ ie,
                            const int* __restrict__ rows) {
    int idx = blockIdx.x * blockDim.x + threadIdx.x;      // float4 / half4 index
    const int total = N_NODES_ * EMB / 4;                 // 2.4M
    if (idx < total) {
        int node = idx >> 4;
        int c4   = idx & 15;
        float4 v;
        if (node < N_USER) v = __ldg((const float4*)ue + node * 16 + c4);
        else               v = __ldg((const float4*)ie + (node - N_USER) * 16 + c4);
        ((float4*)g_all)[node * 64 + c4] = v;
        __half2 h0 = __floats2half2_rn(v.x, v.y);
        __half2 h1 = __floats2half2_rn(v.z, v.w);
        uint2 pk;
        pk.x = *(unsigned*)&h0;
        pk.y = *(unsigned*)&h1;
        ((uint2*)g_ego_h)[idx] = pk;
    }
    if (idx < NNZ_ / 4) {             // fused degree count (cnt pre-zeroed)
        int4 r4 = __ldg((const int4*)rows + idx);
        atomicAdd(&g_row_cnt[r4.x], 1);
        atomicAdd(&g_row_cnt[r4.y], 1);
        atomicAdd(&g_row_cnt[r4.z], 1);
        atomicAdd(&g_row_cnt[r4.w], 1);
    }
}

// ---------------- CSR build: coalesced wave-scan (single block, 1024 thr) ----
__global__ void scan_kernel() {
    __shared__ int warp_sums[32];
    const int NWAVES = (N_NODES_ + 1023) / 1024;   // 147
    int t    = threadIdx.x;
    int lane = t & 31;
    int wid  = t >> 5;
    int carry = 0;
    for (int w = 0; w < NWAVES; w++) {
        int idx = w * 1024 + t;
        int c = 0;
        if (idx < N_NODES_) {
            c = g_row_cnt[idx];
            g_row_cnt[idx] = 0;     // reset for next replay
        }
        int x = c;                  // inclusive warp scan
#pragma unroll
        for (int off = 1; off < 32; off <<= 1) {
            int y = __shfl_up_sync(0xffffffffu, x, off);
            if (lane >= off) x += y;
        }
        if (lane == 31) warp_sums[wid] = x;
        __syncthreads();
        if (wid == 0) {             // scan the 32 warp totals
            int wv = warp_sums[lane];
#pragma unroll
            for (int off = 1; off < 32; off <<= 1) {
                int y = __shfl_up_sync(0xffffffffu, wv, off);
                if (lane >= off) wv += y;
            }
            warp_sums[lane] = wv;   // inclusive over warps
        }
        __syncthreads();
        int warp_excl = (wid > 0) ? warp_sums[wid - 1] : 0;
        int excl = carry + warp_excl + (x - c);
        if (idx < N_NODES_) {
            g_row_off[idx] = excl;
            g_row_cur[idx] = excl;  // cursor starts at row start
        }
        carry += warp_sums[31];     // wave total
        __syncthreads();            // protect warp_sums before next wave
    }
    if (t == 0) g_row_off[N_NODES_] = carry;   // total = NNZ
}

// ---------------- CSR build: scatter edges ------------------------------------
__global__ void scatter_kernel(const int* __restrict__ rows,
                               const int* __restrict__ cols,
                               const int* __restrict__ vals) {
    int q = blockIdx.x * blockDim.x + threadIdx.x;   // octet id
    if (q >= NNZ_ / 8) return;
    int4 ra = __ldg((const int4*)rows + q * 2);
    int4 rb = __ldg((const int4*)rows + q * 2 + 1);
    int4 ca = __ldg((const int4*)cols + q * 2);
    int4 cb = __ldg((const int4*)cols + q * 2 + 1);
    int4 va = __ldg((const int4*)vals + q * 2);      // val bits
    int4 vb = __ldg((const int4*)vals + q * 2 + 1);
    int r[8] = {ra.x, ra.y, ra.z, ra.w, rb.x, rb.y, rb.z, rb.w};
    int c[8] = {ca.x, ca.y, ca.z, ca.w, cb.x, cb.y, cb.z, cb.w};
    int v[8] = {va.x, va.y, va.z, va.w, vb.x, vb.y, vb.z, vb.w};
    int p[8];
#pragma unroll
    for (int u = 0; u < 8; u++) p[u] = atomicAdd(&g_row_cur[r[u]], 1);
#pragma unroll
    for (int u = 0; u < 8; u++) g_edge_s[p[u]] = make_int2(c[u], v[u]);
}

// ---------------- CSR SpMM: fp16 gather (16B/lane), fp32 accum, fp16 store ----
// 8 lanes per row; each lane owns 8 consecutive columns; 4-edge unroll.
__global__ void spmm_csr_kernel() {
    int t = blockIdx.x * blockDim.x + threadIdx.x;
    int r = t >> 3;                 // row id
    if (r >= N_NODES_) return;
    int l = t & 7;                  // lane-slice: columns [l*8, l*8+8)
    int beg = __ldg(&g_row_off[r]);
    int end = __ldg(&g_row_off[r + 1]);
    float a0 = 0.f, a1 = 0.f, a2 = 0.f, a3 = 0.f;
    float a4 = 0.f, a5 = 0.f, a6 = 0.f, a7 = 0.f;
    int e = beg;
    for (; e + 4 <= end; e += 4) {
        int2 E0 = __ldg(&g_edge_s[e + 0]);
        int2 E1 = __ldg(&g_edge_s[e + 1]);
        int2 E2 = __ldg(&g_edge_s[e + 2]);
        int2 E3 = __ldg(&g_edge_s[e + 3]);
        uint4 w0 = __ldg((const uint4*)g_ego_h + E0.x * 8 + l);
        uint4 w1 = __ldg((const uint4*)g_ego_h + E1.x * 8 + l);
        uint4 w2 = __ldg((const uint4*)g_ego_h + E2.x * 8 + l);
        uint4 w3 = __ldg((const uint4*)g_ego_h + E3.x * 8 + l);
        float v0 = __int_as_float(E0.y);
        float v1 = __int_as_float(E1.y);
        float v2 = __int_as_float(E2.y);
        float v3 = __int_as_float(E3.y);
#define ACC_EDGE(W, V)                                              \
        {                                                           \
            float2 p0 = __half22float2(*(const __half2*)&W.x);     \
            float2 p1 = __half22float2(*(const __half2*)&W.y);     \
            float2 p2 = __half22float2(*(const __half2*)&W.z);     \
            float2 p3 = __half22float2(*(const __half2*)&W.w);     \
            a0 += p0.x * V; a1 += p0.y * V;                         \
            a2 += p1.x * V; a3 += p1.y * V;                         \
            a4 += p2.x * V; a5 += p2.y * V;                         \
            a6 += p3.x * V; a7 += p3.y * V;                         \
        }
        ACC_EDGE(w0, v0)
        ACC_EDGE(w1, v1)
        ACC_EDGE(w2, v2)
        ACC_EDGE(w3, v3)
    }
    for (; e < end; e++) {
        int2 E = __ldg(&g_edge_s[e]);
        uint4 w = __ldg((const uint4*)g_ego_h + E.x * 8 + l);
        float v = __int_as_float(E.y);
        ACC_EDGE(w, v)
    }
#undef ACC_EDGE
    __half2 h0 = __floats2half2_rn(a0, a1);
    __half2 h1 = __floats2half2_rn(a2, a3);
    __half2 h2 = __floats2half2_rn(a4, a5);
    __half2 h3 = __floats2half2_rn(a6, a7);
    uint4 pk;
    pk.x = *(unsigned*)&h0; pk.y = *(unsigned*)&h1;
    pk.z = *(unsigned*)&h2; pk.w = *(unsigned*)&h3;
    ((uint4*)g_side_h)[r * 8 + l] = pk;        // one STG.128 per lane
}

// ---------------- tensor-core transform + leaky_relu + L2-normalize ----------
// out = leaky([S|P](64x128) @ [Wg;Wb](128x64) + b), then row-normalize.
// S, P staged directly from fp16 state (P = hmul2(ego_h, side_h)).
__global__ void transform_kernel(const float* __restrict__ Wgc,
                                 const float* __restrict__ bgc,
                                 const float* __restrict__ Wbi,
                                 const float* __restrict__ bbi,
                                 int layer) {
    extern __shared__ char sh[];
    __half* A_h = (__half*)(sh + SH_A);   // [64][A_LD]
    __half* B_h = (__half*)(sh + SH_B);   // [128][B_LD]
    float*  C_f = (float*) (sh + SH_C);   // [64][C_LD]
    float*  bs  = (float*) (sh + SH_BS);  // [64]

    const int tid = threadIdx.x;
    const int rowBase = blockIdx.x * 64;

    // stage B = [Wg; Wb] as fp16 (coalesced float4 loads)
    for (int i = tid; i < 1024; i += 256) {
        int k  = i >> 4;              // 0..63
        int n4 = i & 15;
        float4 wg = __ldg((const float4*)Wgc + i);
        float4 wb = __ldg((const float4*)Wbi + i);
        __half2* dg = (__half2*)&B_h[k * B_LD + n4 * 4];
        dg[0] = __floats2half2_rn(wg.x, wg.y);
        dg[1] = __floats2half2_rn(wg.z, wg.w);
        __half2* db = (__half2*)&B_h[(64 + k) * B_LD + n4 * 4];
        db[0] = __floats2half2_rn(wb.x, wb.y);
        db[1] = __floats2half2_rn(wb.z, wb.w);
    }
    if (tid < 64) bs[tid] = __ldg(bgc + tid) + __ldg(bbi + tid);

    // stage A = [S | ego*S] straight from fp16 state (coalesced uint2 loads)
    for (int i = tid; i < 1024; i += 256) {
        int r  = i >> 4;
        int c4 = i & 15;
        int gr = rowBase + r;
        uint2 sb = make_uint2(0u, 0u);
        uint2 eb = make_uint2(0u, 0u);
        if (gr < N_NODES_) {
            sb = ((const uint2*)g_side_h)[gr * 16 + c4];
            eb = ((const uint2*)g_ego_h )[gr * 16 + c4];
        }
        __half2 s0 = *(const __half2*)&sb.x;
        __half2 s1 = *(const __half2*)&sb.y;
        __half2 e0 = *(const __half2*)&eb.x;
        __half2 e1 = *(const __half2*)&eb.y;
        __half2* ds = (__half2*)&A_h[r * A_LD + c4 * 4];
        ds[0] = s0;
        ds[1] = s1;
        __half2* dp = (__half2*)&A_h[r * A_LD + 64 + c4 * 4];
        dp[0] = __hmul2(e0, s0);
        dp[1] = __hmul2(e1, s1);
    }
    __syncthreads();

    // wmma: 8 warps, each owns one 16-row tile slice x 2 col tiles
    {
        int w = tid >> 5;             // 0..7
        int rt = w >> 1;              // row tile 0..3
        int ct = (w & 1) * 2;         // col tiles ct, ct+1
        wmma::fragment<wmma::accumulator, 16, 16, 16, float> c0, c1;
        wmma::fill_fragment(c0, 0.0f);
        wmma::fill_fragment(c1, 0.0f);
#pragma unroll
        for (int k = 0; k < 8; k++) {
            wmma::fragment<wmma::matrix_a, 16, 16, 16, __half, wmma::row_major> a;
            wmma::fragment<wmma::matrix_b, 16, 16, 16, __half, wmma::row_major> b0, b1;
            wmma::load_matrix_sync(a, &A_h[rt * 16 * A_LD + k * 16], A_LD);
            wmma::load_matrix_sync(b0, &B_h[k * 16 * B_LD + ct * 16], B_LD);
            wmma::load_matrix_sync(b1, &B_h[k * 16 * B_LD + (ct + 1) * 16], B_LD);
            wmma::mma_sync(c0, a, b0, c0);
            wmma::mma_sync(c1, a, b1, c1);
        }
        wmma::store_matrix_sync(&C_f[rt * 16 * C_LD + ct * 16], c0, C_LD, wmma::mem_row_major);
        wmma::store_matrix_sync(&C_f[rt * 16 * C_LD + (ct + 1) * 16], c1, C_LD, wmma::mem_row_major);
    }
    __syncthreads();

    // epilogue: bias + leaky, row-norm across 16 tx lanes, write back
    const int tx = tid & 15;
    const int ty = tid >> 4;
    const int colBase = tx * 4;
    float b0 = bs[colBase + 0], b1 = bs[colBase + 1];
    float b2 = bs[colBase + 2], b3 = bs[colBase + 3];
#pragma unroll
    for (int i = 0; i < 4; i++) {
        int r = ty * 4 + i;
        float4 xc = *(const float4*)&C_f[r * C_LD + colBase];
        float x0 = xc.x + b0;
        float x1 = xc.y + b1;
        float x2 = xc.z + b2;
        float x3 = xc.w + b3;
        x0 = fmaxf(x0, NEG_SLOPE * x0);
        x1 = fmaxf(x1, NEG_SLOPE * x1);
        x2 = fmaxf(x2, NEG_SLOPE * x2);
        x3 = fmaxf(x3, NEG_SLOPE * x3);
        float sq = x0 * x0 + x1 * x1 + x2 * x2 + x3 * x3;
#pragma unroll
        for (int off = 1; off < 16; off <<= 1)
            sq += __shfl_xor_sync(0xffffffffu, sq, off);
        int gr = rowBase + r;
        if (gr < N_NODES_) {
            float inv = 1.0f / fmaxf(sqrtf(sq), EPS_);
            *(float4*)&g_all[(size_t)gr * 256 + (layer + 1) * 64 + colBase] =
                make_float4(x0 * inv, x1 * inv, x2 * inv, x3 * inv);
            if (layer < N_LAYERS - 1) {
                __half2 h0 = __floats2half2_rn(x0, x1);
                __half2 h1 = __floats2half2_rn(x2, x3);
                uint2 pk;
                pk.x = *(unsigned*)&h0;
                pk.y = *(unsigned*)&h1;
                *(uint2*)&g_ego_h[(size_t)gr * EMB + colBase] = pk;
            }
        }
    }
}

// ---------------- GMF head: sigmoid((u*i)@W_out + b_out) ---------------------
__global__ void head_kernel(const int* __restrict__ uidx,
                            const int* __restrict__ iidx,
                            const float* __restrict__ Wout,
                            const float* __restrict__ bout,
                            float* __restrict__ out) {
    int gw = (blockIdx.x * blockDim.x + threadIdx.x) >> 5;
    if (gw >= BATCH_) return;
    int lane = threadIdx.x & 31;
    int u  = __ldg(&uidx[gw]);
    int it = __ldg(&iidx[gw]) + N_USER;
    const float4* ur = (const float4*)(g_all + (size_t)u  * 256);
    const float4* ir = (const float4*)(g_all + (size_t)it * 256);
    const float4* w4 = (const float4*)Wout;
    float acc = 0.f;
#pragma unroll
    for (int q = 0; q < 2; q++) {
        int c = lane + q * 32;
        float4 a = ur[c];
        float4 b = ir[c];
        float4 w = __ldg(&w4[c]);
        acc += a.x * b.x * w.x + a.y * b.y * w.y + a.z * b.z * w.z + a.w * b.w * w.w;
    }
#pragma unroll
    for (int off = 16; off; off >>= 1)
        acc += __shfl_xor_sync(0xffffffffu, acc, off);
    if (lane == 0) {
        float z = acc + __ldg(bout);
        out[gw] = 1.0f / (1.0f + expf(-z));
    }
}

// ---------------- launch ------------------------------------------------------
extern "C" void kernel_launch(void* const* d_in, const int* in_sizes, int n_in,
                              void* d_out, int out_size) {
    const int*   user_idx = (const int*)  d_in[0];
    const int*   item_idx = (const int*)  d_in[1];
    const int*   adj_rows = (const int*)  d_in[2];
    const int*   adj_cols = (const int*)  d_in[3];
    const int*   adj_vals = (const int*)  d_in[4];   // raw bits for scatter
    const float* user_emb = (const float*)d_in[5];
    const float* item_emb = (const float*)d_in[6];
    const float* W_gc     = (const float*)d_in[7];
    const float* b_gc     = (const float*)d_in[8];
    const float* W_bi     = (const float*)d_in[9];
    const float* b_bi     = (const float*)d_in[10];
    const float* W_out    = (const float*)d_in[11];
    const float* b_out    = (const float*)d_in[12];
    float* out = (float*)d_out;

    cudaFuncSetAttribute(transform_kernel,
                         cudaFuncAttributeMaxDynamicSharedMemorySize, SH_TOT);

    const int vec_blocks = (N_NODES_ * EMB / 4) / 256;   // 9375 (covers NNZ/4=1.2M too)
    init_kernel<<<vec_blocks, 256>>>(user_emb, item_emb, adj_rows);

    scan_kernel<<<1, 1024>>>();
    scatter_kernel<<<(NNZ_ / 8 + 255) / 256, 256>>>(adj_rows, adj_cols, adj_vals);

    const int spmm_blocks = (N_NODES_ * 8 + 255) / 256;  // 4688
    const int tile_blocks = (N_NODES_ + 63) / 64;        // 2344

    for (int l = 0; l < N_LAYERS; l++) {
        spmm_csr_kernel<<<spmm_blocks, 256>>>();
        transform_kernel<<<tile_blocks, 256, SH_TOT>>>(W_gc + l * EMB * EMB,
                                                       b_gc + l * EMB,
                                                       W_bi + l * EMB * EMB,
                                                       b_bi + l * EMB,
                                                       l);
    }

    head_kernel<<<(BATCH_ * 32) / 256, 256>>>(user_idx, item_idx, W_out, b_out, out);
}